// round 12
// baseline (speedup 1.0000x reference)
#include <cuda_runtime.h>
#include <math.h>

typedef unsigned long long U64;

#define TD 200
#define BATCH 32
#define TE 256
#define EDIM 512
#define NM 80
#define ADIM 128
#define K1 1792
#define K2 2048
#define NBLK 128
#define NTHR 256

// ---------------- persistent device state (no allocations) ----------------
__device__ float g_x[TD * BATCH * 256];      // prenet outputs, all steps
__device__ float g_pe[BATCH * TE * ADIM];    // proc_enc = inputs @ W_enc
__device__ float g_cat1[2][BATCH * K1];      // [x(256) | ctx(512) | h1(1024)]
__device__ float g_cat2[2][BATCH * K2];      // [h1(1024) | h2(1024)]
__device__ float g_c1[BATCH * 1024];
__device__ float g_c2[BATCH * 1024];
__device__ float g_awcum[BATCH * TE];
__device__ U64 g_barcnt;                     // monotone within a launch; reset at end
__device__ unsigned g_done;

// ---------------- f32x2 helpers ----------------
__device__ __forceinline__ U64 pk2(float x, float y) {
    U64 r; asm("mov.b64 %0, {%1, %2};" : "=l"(r) : "f"(x), "f"(y)); return r;
}
__device__ __forceinline__ void upk2(U64 v, float& lo, float& hi) {
    asm("mov.b64 {%0, %1}, %2;" : "=f"(lo), "=f"(hi) : "l"(v));
}
__device__ __forceinline__ void fma2(U64& d, U64 a, U64 b) {
    asm("fma.rn.f32x2 %0, %1, %2, %0;" : "+l"(d) : "l"(a), "l"(b));
}
__device__ __forceinline__ float sigm(float x) { return 1.f / (1.f + expf(-x)); }

// ---------------- grid barrier (all NBLK blocks co-resident) ----------------
__device__ __forceinline__ void gridbar(U64& target) {
    __threadfence();            // release: publish this block's stores
    __syncthreads();
    if (threadIdx.x == 0) {
        target += NBLK;
        atomicAdd(&g_barcnt, 1ULL);
        while (*((volatile U64*)&g_barcnt) < target) {}
    }
    __syncthreads();
    __threadfence();            // acquire: discard stale L1 for cross-SM data
}

// ---------------- fused GEMM (M=32, N=4096) + LSTM cell ----------------
// Block owns 8 h-cols (n0 = blk*8). Thread (r = tid>>3, hc = tid&7) computes
// rows r for gate-pairs (i,f) and (g,o) of h-col n0+hc via fma.rn.f32x2.
__device__ void gemm_cell(U64* SMU, const float* __restrict__ Am, int lda,
                          const float* __restrict__ Wi, const float* __restrict__ Wh,
                          int ksplit, int K, const float* __restrict__ bias,
                          float* cst, float* d1, int s1, float* d2, int s2) {
    U64* sAd = SMU;            // [32][65] duplicated A pairs (padded: conflict-free)
    U64* sW  = SMU + 2080;     // [64][16] : slot hc*2+0 = (i,f), hc*2+1 = (g,o)
    float* sWf = (float*)sW;
    int tid = threadIdx.x;
    int n0 = blockIdx.x * 8;
    int r = tid >> 3, hc = tid & 7;
    U64 aIF = 0, aGO = 0;

    for (int k0 = 0; k0 < K; k0 += 64) {
        for (int i = tid; i < 2048; i += NTHR) {
            int rr = i >> 6, kk = i & 63;
            float v = Am[rr * lda + k0 + kk];
            sAd[rr * 65 + kk] = pk2(v, v);
        }
        for (int i = tid; i < 2048; i += NTHR) {
            int kk = i >> 5, g = (i >> 3) & 3, cc = i & 7;
            int kr = k0 + kk;
            const float* Wr = (kr < ksplit) ? (Wi + (size_t)kr * 4096)
                                            : (Wh + (size_t)(kr - ksplit) * 4096);
            sWf[(kk * 16 + cc * 2 + (g >> 1)) * 2 + (g & 1)] = Wr[g * 1024 + n0 + cc];
        }
        __syncthreads();
        const U64* ar = sAd + r * 65;
        const U64* wr = sW + hc * 2;
#pragma unroll 8
        for (int k = 0; k < 64; k++) {
            U64 a = ar[k];
            fma2(aIF, a, wr[k * 16]);
            fma2(aGO, a, wr[k * 16 + 1]);
        }
        __syncthreads();
    }
    int c = n0 + hc;
    float gi, gf, gg, go;
    upk2(aIF, gi, gf);
    upk2(aGO, gg, go);
    float ii = sigm(gi + bias[c]);
    float ff = sigm(gf + bias[1024 + c]);
    float gt = tanhf(gg + bias[2048 + c]);
    float oo = sigm(go + bias[3072 + c]);
    float cn = ff * cst[r * 1024 + c] + ii * gt;
    float hh = oo * tanhf(cn);
    cst[r * 1024 + c] = cn;
    d1[r * s1 + c] = hh;
    if (d2) d2[r * s2 + c] = hh;
}

// ---------------- the whole decoder: one persistent kernel ----------------
__global__ void __launch_bounds__(NTHR, 1) decoder_kernel(
    const float* __restrict__ inputs, const float* __restrict__ pmels,
    const float* __restrict__ W_enc, const float* __restrict__ W_q,
    const float* __restrict__ conv_w, const float* __restrict__ conv_b,
    const float* __restrict__ W_loc, const float* __restrict__ v_e,
    const float* __restrict__ pw1, const float* __restrict__ pb1,
    const float* __restrict__ pw2, const float* __restrict__ pb2,
    const float* __restrict__ Wi1, const float* __restrict__ Wh1,
    const float* __restrict__ bl1, const float* __restrict__ Wi2,
    const float* __restrict__ Wh2, const float* __restrict__ bl2,
    const float* __restrict__ Wp, const float* __restrict__ bp,
    float* __restrict__ out) {
    __shared__ U64 SMU[6000];              // 48000 B, unioned across phases
    float* SMF = (float*)SMU;
    int tid = threadIdx.x, blk = blockIdx.x;
    int w = tid >> 5, lane = tid & 31;
    U64 target = 0;

    // ---- P0: prenet for all (t, b) ----
    {
        float* smel = SMF;        // 80
        float* sx1 = SMF + 128;   // 256
        for (int task = blk; task < TD * BATCH; task += NBLK) {
            int t = task / BATCH, b = task - t * BATCH;
            if (tid < 80) smel[tid] = (t == 0) ? 0.f : pmels[(b * 80 + tid) * TD + (t - 1)];
            __syncthreads();
            float a1 = pb1[tid];
#pragma unroll 8
            for (int k = 0; k < 80; k++) a1 += smel[k] * pw1[k * 256 + tid];
            sx1[tid] = fmaxf(a1, 0.f);
            __syncthreads();
            float a2 = pb2[tid];
#pragma unroll 8
            for (int k = 0; k < 256; k++) a2 += sx1[k] * pw2[k * 256 + tid];
            g_x[(t * BATCH + b) * 256 + tid] = fmaxf(a2, 0.f);
            __syncthreads();
        }
    }
    gridbar(target);

    // ---- P1: proc_enc (8192 row-tasks, 2 per iteration) + P2: init ----
    {
        float* sinp = SMF;  // 1024
        int tau = tid >> 7, a = tid & 127;
        for (int pair0 = blk * 64; pair0 < blk * 64 + 64; pair0 += 2) {
            for (int i = tid; i < 1024; i += NTHR) {
                int tsk = pair0 + (i >> 9), k = i & 511;
                int b = tsk >> 8, tt = tsk & 255;
                sinp[i] = inputs[((size_t)(b * 256 + tt)) * 512 + k];
            }
            __syncthreads();
            int tsk = pair0 + tau;
            int b = tsk >> 8, tt = tsk & 255;
            const float* sp = sinp + tau * 512;
            float acc = 0.f;
#pragma unroll 4
            for (int k = 0; k < 512; k++) acc += sp[k] * W_enc[k * 128 + a];
            g_pe[((size_t)(b * 256 + tt)) * 128 + a] = acc;
            __syncthreads();
        }
        int gtid = blk * NTHR + tid, gn = NBLK * NTHR;
        for (int j = gtid; j < BATCH * K1; j += gn) {
            int b = j / K1, c = j - b * K1;
            g_cat1[0][j] = (c < 256) ? g_x[b * 256 + c] : 0.f;
        }
        for (int j = gtid; j < BATCH * K2; j += gn) g_cat2[0][j] = 0.f;
        for (int j = gtid; j < BATCH * 1024; j += gn) { g_c1[j] = 0.f; g_c2[j] = 0.f; }
        for (int j = gtid; j < BATCH * TE; j += gn) g_awcum[j] = 0.f;
    }
    gridbar(target);

    // ---- main loop: 200 steps, 3 grid barriers each ----
    for (int t = 0; t < TD; t++) {
        int par = t & 1;
        float* c1p = g_cat1[par];
        float* c1q = g_cat1[par ^ 1];
        float* c2p = g_cat2[par];
        float* c2q = g_cat2[par ^ 1];

        // G1: h1 = cell1(cat1) -> cat1-next[768:] and cat2-cur[0:1024]
        gemm_cell(SMU, c1p, K1, Wi1, Wh1, 768, K1, bl1, g_c1, c1q + 768, K1, c2p, K2);
        gridbar(target);
        // G2: h2 = cell2(cat2) -> cat2-next[1024:]
        gemm_cell(SMU, c2p, K2, Wi2, Wh2, 1024, K2, bl2, g_c2, c2q + 1024, K2, (float*)0, 0);
        gridbar(target);

        // ATT: blocks 0..31, one batch row each
        if (blk < BATCH) {
            float* sWloc = SMF;          // 4096
            float* sh2   = SMF + 4096;   // 1024  (contiguous with sctx for proj)
            float* sctx  = SMF + 5120;   // 512
            float* sq    = SMF + 5632;   // 128
            float* sve   = SMF + 5760;   // 128
            float* scw   = SMF + 5888;   // 992
            float* scb   = SMF + 6880;   // 32
            float* sawc  = SMF + 6912;   // 256
            float* se    = SMF + 7168;   // 256
            float* saw   = SMF + 7424;   // 256
            float* sred  = SMF + 7680;   // 32
            float* spp   = SMF + 7712;   // 160
            float* su    = SMF + 7872;   // 256 (per-warp u staging)
            const float* h2r = c2q + blk * K2 + 1024;

            for (int i = tid; i < 4096; i += NTHR) sWloc[i] = W_loc[i];
            for (int i = tid; i < 1024; i += NTHR) sh2[i] = h2r[i];
            for (int i = tid; i < 992; i += NTHR) scw[i] = conv_w[i];
            if (tid < 32) scb[tid] = conv_b[tid];
            if (tid < 128) sve[tid] = v_e[tid];
            sawc[tid] = g_awcum[blk * TE + tid];
            __syncthreads();

            // q = h2 @ W_q
            if (tid < 128) {
                float q0 = 0.f, q1 = 0.f;
#pragma unroll 4
                for (int k = 0; k < 1024; k += 2) {
                    q0 += sh2[k] * W_q[k * 128 + tid];
                    q1 += sh2[k + 1] * W_q[(k + 1) * 128 + tid];
                }
                sq[tid] = q0 + q1;
            }
            __syncthreads();

            // conv + energies: warp w handles t-slots w*32 .. w*32+31
            for (int ti = 0; ti < 32; ti++) {
                int tt = w * 32 + ti;
                float u = scb[lane];
#pragma unroll
                for (int j = 0; j < 31; j++) {
                    int idx = tt + j - 15;
                    float av = (idx >= 0 && idx < TE) ? sawc[idx] : 0.f;
                    u += av * scw[lane * 31 + j];
                }
                su[w * 32 + lane] = u;
                __syncwarp();
                float l0 = 0.f, l1 = 0.f, l2 = 0.f, l3 = 0.f;
#pragma unroll
                for (int c = 0; c < 32; c++) {
                    float uc = su[w * 32 + c];
                    l0 += uc * sWloc[c * 128 + lane];
                    l1 += uc * sWloc[c * 128 + lane + 32];
                    l2 += uc * sWloc[c * 128 + lane + 64];
                    l3 += uc * sWloc[c * 128 + lane + 96];
                }
                const float* per = g_pe + ((size_t)(blk * TE + tt)) * 128;
                float ep = tanhf(sq[lane] + l0 + per[lane]) * sve[lane]
                         + tanhf(sq[lane + 32] + l1 + per[lane + 32]) * sve[lane + 32]
                         + tanhf(sq[lane + 64] + l2 + per[lane + 64]) * sve[lane + 64]
                         + tanhf(sq[lane + 96] + l3 + per[lane + 96]) * sve[lane + 96];
#pragma unroll
                for (int o = 16; o; o >>= 1) ep += __shfl_xor_sync(0xffffffffu, ep, o);
                if (lane == 0) se[tt] = ep;
                __syncwarp();
            }
            __syncthreads();

            // softmax over 256
            float e = se[tid];
            float m = e;
#pragma unroll
            for (int o = 16; o; o >>= 1) m = fmaxf(m, __shfl_xor_sync(0xffffffffu, m, o));
            if (lane == 0) sred[w] = m;
            __syncthreads();
            float mm = sred[0];
#pragma unroll
            for (int i = 1; i < 8; i++) mm = fmaxf(mm, sred[i]);
            float ex = expf(e - mm);
            float s = ex;
#pragma unroll
            for (int o = 16; o; o >>= 1) s += __shfl_xor_sync(0xffffffffu, s, o);
            __syncthreads();
            if (lane == 0) sred[w] = s;
            __syncthreads();
            float ss = 0.f;
#pragma unroll
            for (int i = 0; i < 8; i++) ss += sred[i];
            float aw = ex / ss;
            saw[tid] = aw;
            g_awcum[blk * TE + tid] = sawc[tid] + aw;
            __syncthreads();

            // context (512 cols, 2 per thread) + stage into cat1-next
#pragma unroll
            for (int cc = 0; cc < 2; cc++) {
                int c = tid + cc * 256;
                float acc = 0.f;
                const float* ib = inputs + (size_t)blk * TE * EDIM + c;
#pragma unroll 4
                for (int tt2 = 0; tt2 < 256; tt2++) acc += saw[tt2] * ib[(size_t)tt2 * EDIM];
                sctx[c] = acc;
                c1q[blk * K1 + 256 + c] = acc;
            }
            if (t + 1 < TD) c1q[blk * K1 + tid] = g_x[((t + 1) * BATCH + blk) * 256 + tid];
            __syncthreads();

            // out = concat(h2, ctx) @ Wp + bp
            if (tid < 160) {
                int col = tid >> 1, half = tid & 1, k0 = half * 768;
                float acc = 0.f;
                const float* scat = sh2;   // sh2(1024) + sctx(512) contiguous
#pragma unroll 4
                for (int k = 0; k < 768; k++) acc += scat[k0 + k] * Wp[(k0 + k) * NM + col];
                spp[tid] = acc;
            }
            __syncthreads();
            if (tid < 80)
                out[(size_t)t * (BATCH * NM) + blk * NM + tid] =
                    spp[2 * tid] + spp[2 * tid + 1] + bp[tid];
        }
        gridbar(target);
    }

    // ---- reset barrier state for deterministic graph replays ----
    __syncthreads();
    if (tid == 0) {
        __threadfence();
        atomicAdd(&g_done, 1u);
        if (blk == 0) {
            while (*((volatile unsigned*)&g_done) < NBLK) {}
            g_barcnt = 0;
            g_done = 0;
            __threadfence();
        }
    }
}

// ---------------- launch: ONE graph node ----------------
extern "C" void kernel_launch(void* const* d_in, const int* in_sizes, int n_in,
                              void* d_out, int out_size) {
    decoder_kernel<<<NBLK, NTHR>>>(
        (const float*)d_in[0],  (const float*)d_in[1],  (const float*)d_in[2],
        (const float*)d_in[3],  (const float*)d_in[4],  (const float*)d_in[5],
        (const float*)d_in[6],  (const float*)d_in[7],  (const float*)d_in[8],
        (const float*)d_in[9],  (const float*)d_in[10], (const float*)d_in[11],
        (const float*)d_in[12], (const float*)d_in[13], (const float*)d_in[14],
        (const float*)d_in[15], (const float*)d_in[16], (const float*)d_in[17],
        (const float*)d_in[18], (const float*)d_in[19], (float*)d_out);
}

// round 13
// speedup vs baseline: 2.1929x; 2.1929x over previous
#include <cuda_runtime.h>
#include <math.h>

typedef unsigned long long U64;

#define TD 200
#define BATCH 32
#define TE 256
#define EDIM 512
#define NM 80
#define K1 1792
#define K2 2048
#define NBLK 128
#define NTHR 512
#define SMEM_BYTES 65536

// ---------------- persistent device state (module-load, no runtime alloc) ----------------
__device__ float g_x[TD * BATCH * 256];        // prenet outputs, all steps
__device__ float g_pe[BATCH * TE * 128];       // proc_enc
__device__ float g_cat1[2][K1 * 32];           // k-major [K1][32rows]: [x|ctx|h1]
__device__ float g_cat2[2][K2 * 32];           // [h1|h2]
__device__ float g_c1[BATCH * 1024];
__device__ float g_c2[BATCH * 1024];
__device__ float g_awcum[BATCH * TE];
__device__ U64 g_w1[(size_t)NBLK * K1 * 16];   // repacked gate-paired weights L1
__device__ U64 g_w2[(size_t)NBLK * K2 * 16];   // L2
__device__ U64 g_barcnt;
__device__ unsigned g_done;

// ---------------- f32x2 helpers ----------------
__device__ __forceinline__ U64 pk2(float x, float y) {
    U64 r; asm("mov.b64 %0, {%1, %2};" : "=l"(r) : "f"(x), "f"(y)); return r;
}
__device__ __forceinline__ void upk2(U64 v, float& lo, float& hi) {
    asm("mov.b64 {%0, %1}, %2;" : "=f"(lo), "=f"(hi) : "l"(v));
}
__device__ __forceinline__ void fma2(U64& d, U64 a, U64 b) {
    asm("fma.rn.f32x2 %0, %1, %2, %0;" : "+l"(d) : "l"(a), "l"(b));
}
__device__ __forceinline__ float sigm(float x) { return 1.f / (1.f + expf(-x)); }

// ---------------- grid barrier ----------------
__device__ __forceinline__ void gridbar(U64& target) {
    __threadfence();
    __syncthreads();
    if (threadIdx.x == 0) {
        target += NBLK;
        atomicAdd(&g_barcnt, 1ULL);
        while (*((volatile U64*)&g_barcnt) < target) {}
    }
    __syncthreads();
    __threadfence();
}

// ---------------- GEMM (M=32, per-block 32 cols) + LSTM cell, no smem staging ----------------
// Warp w owns k-slice [w*KS, (w+1)*KS). Lane: rg=lane>>3 (rows rg*8..+7), hc=lane&7.
// Thread accumulates 8 rows x {IF,GO} pairs = 16 U64.
__device__ void gemm_cell(U64* swr, const float* __restrict__ A,
                          const U64* __restrict__ wp, int KS,
                          const float* __restrict__ bias,
                          float* __restrict__ cst,
                          float* __restrict__ d1, float* __restrict__ d2) {
    int tid = threadIdx.x, w = tid >> 5, lane = tid & 31;
    int rg = lane >> 3, hc = lane & 7;
    U64 acc[16];
#pragma unroll
    for (int i = 0; i < 16; i++) acc[i] = 0;
    int kbeg = w * KS;
    const float* ap = A + (size_t)kbeg * 32 + rg * 8;
    const ulonglong2* wpp = (const ulonglong2*)(wp + (size_t)kbeg * 16) + hc;
#pragma unroll 4
    for (int k = 0; k < KS; k++) {
        float4 a0 = *(const float4*)ap;
        float4 a1 = *(const float4*)(ap + 4);
        ulonglong2 wv = *wpp;
        ap += 32; wpp += 8;
        U64 p;
        p = pk2(a0.x, a0.x); fma2(acc[0],  p, wv.x); fma2(acc[1],  p, wv.y);
        p = pk2(a0.y, a0.y); fma2(acc[2],  p, wv.x); fma2(acc[3],  p, wv.y);
        p = pk2(a0.z, a0.z); fma2(acc[4],  p, wv.x); fma2(acc[5],  p, wv.y);
        p = pk2(a0.w, a0.w); fma2(acc[6],  p, wv.x); fma2(acc[7],  p, wv.y);
        p = pk2(a1.x, a1.x); fma2(acc[8],  p, wv.x); fma2(acc[9],  p, wv.y);
        p = pk2(a1.y, a1.y); fma2(acc[10], p, wv.x); fma2(acc[11], p, wv.y);
        p = pk2(a1.z, a1.z); fma2(acc[12], p, wv.x); fma2(acc[13], p, wv.y);
        p = pk2(a1.w, a1.w); fma2(acc[14], p, wv.x); fma2(acc[15], p, wv.y);
    }
    // write per-warp partials: pairIdx = row*16 + hc*2 + p
    U64* dst = swr + w * 512 + (rg * 8) * 16 + hc * 2;
#pragma unroll
    for (int i = 0; i < 8; i++) {
        ulonglong2 v; v.x = acc[2 * i]; v.y = acc[2 * i + 1];
        *(ulonglong2*)(dst + i * 16) = v;
    }
    __syncthreads();
    // reduce 16 partials (fixed order), store into slot 0
    {
        float lo = 0.f, hi = 0.f;
#pragma unroll
        for (int ww = 0; ww < 16; ww++) {
            float l, h; upk2(swr[ww * 512 + tid], l, h);
            lo += l; hi += h;
        }
        swr[tid] = pk2(lo, hi);
    }
    __syncthreads();
    if (tid < 256) {
        int row = tid >> 3, c8 = tid & 7;
        int c = blockIdx.x * 8 + c8;
        float gi, gf, gg, go;
        upk2(swr[row * 16 + c8 * 2], gi, gf);
        upk2(swr[row * 16 + c8 * 2 + 1], gg, go);
        float ii = sigm(gi + bias[c]);
        float ff = sigm(gf + bias[1024 + c]);
        float gt = tanhf(gg + bias[2048 + c]);
        float oo = sigm(go + bias[3072 + c]);
        float cn = ff * cst[row * 1024 + c] + ii * gt;
        float hh = oo * tanhf(cn);
        cst[row * 1024 + c] = cn;
        d1[(size_t)c * 32 + row] = hh;
        if (d2) d2[(size_t)c * 32 + row] = hh;
    }
    __syncthreads();
}

// ---------------- the whole decoder ----------------
__global__ void __launch_bounds__(NTHR, 1) decoder_kernel(
    const float* __restrict__ inputs, const float* __restrict__ pmels,
    const float* __restrict__ W_enc, const float* __restrict__ W_q,
    const float* __restrict__ conv_w, const float* __restrict__ conv_b,
    const float* __restrict__ W_loc, const float* __restrict__ v_e,
    const float* __restrict__ pw1, const float* __restrict__ pb1,
    const float* __restrict__ pw2, const float* __restrict__ pb2,
    const float* __restrict__ Wi1, const float* __restrict__ Wh1,
    const float* __restrict__ bl1, const float* __restrict__ Wi2,
    const float* __restrict__ Wh2, const float* __restrict__ bl2,
    const float* __restrict__ Wp, const float* __restrict__ bp,
    float* __restrict__ out) {
    extern __shared__ U64 SMU[];
    float* SMF = (float*)SMU;
    int tid = threadIdx.x, blk = blockIdx.x;
    int lane = tid & 31;
    size_t gtid = (size_t)blk * NTHR + tid;
    size_t gn = (size_t)NBLK * NTHR;
    U64 target = 0;

    // ---- P0: prenet, 2 tasks per block-iteration ----
    {
        float* smel = SMF;        // [2][128]
        float* sx1 = SMF + 256;   // [2][256]
        int sub = tid >> 8, j = tid & 255;
        for (int tp = blk * 2; tp < TD * BATCH; tp += NBLK * 2) {
            int task = tp + sub;
            int t = task >> 5, b = task & 31;
            if (j < 80) smel[sub * 128 + j] =
                (t == 0) ? 0.f : pmels[(b * 80 + j) * TD + (t - 1)];
            __syncthreads();
            float a1 = pb1[j];
#pragma unroll 8
            for (int k = 0; k < 80; k++) a1 += smel[sub * 128 + k] * pw1[k * 256 + j];
            sx1[sub * 256 + j] = fmaxf(a1, 0.f);
            __syncthreads();
            float a2 = pb2[j];
#pragma unroll 8
            for (int k = 0; k < 256; k++) a2 += sx1[sub * 256 + k] * pw2[k * 256 + j];
            g_x[(size_t)task * 256 + j] = fmaxf(a2, 0.f);
            __syncthreads();
        }
    }
    gridbar(target);

    // ---- P1: proc_enc + weight repack + state init ----
    {
        int sub = tid >> 7, a = tid & 127;
        for (int tp = blk * 4; tp < BATCH * TE; tp += NBLK * 4) {
            int task = tp + sub;
            const float* ip = inputs + (size_t)task * 512;
            float acc = 0.f;
#pragma unroll 4
            for (int k = 0; k < 512; k++) acc += ip[k] * W_enc[k * 128 + a];
            g_pe[(size_t)task * 128 + a] = acc;
        }
        // repack L1 weights
        size_t n1 = (size_t)NBLK * K1 * 16;
        for (size_t i = gtid; i < n1; i += gn) {
            int p = (int)(i & 1);
            int hc = (int)((i >> 1) & 7);
            size_t r = i >> 4;
            int k = (int)(r % K1);
            int b2 = (int)(r / K1);
            int c = b2 * 8 + hc;
            const float* Wr = (k < 768) ? (Wi1 + (size_t)k * 4096)
                                        : (Wh1 + (size_t)(k - 768) * 4096);
            g_w1[i] = pk2(Wr[(p * 2) * 1024 + c], Wr[(p * 2 + 1) * 1024 + c]);
        }
        // repack L2 weights
        size_t n2 = (size_t)NBLK * K2 * 16;
        for (size_t i = gtid; i < n2; i += gn) {
            int p = (int)(i & 1);
            int hc = (int)((i >> 1) & 7);
            size_t r = i >> 4;
            int k = (int)(r & (K2 - 1));
            int b2 = (int)(r >> 11);
            int c = b2 * 8 + hc;
            const float* Wr = (k < 1024) ? (Wi2 + (size_t)k * 4096)
                                         : (Wh2 + (size_t)(k - 1024) * 4096);
            g_w2[i] = pk2(Wr[(p * 2) * 1024 + c], Wr[(p * 2 + 1) * 1024 + c]);
        }
        // init state (cat layout is k-major [K][32])
        for (size_t i = gtid; i < (size_t)K1 * 32; i += gn) {
            int k = (int)(i >> 5), b = (int)(i & 31);
            g_cat1[0][i] = (k < 256) ? g_x[(size_t)b * 256 + k] : 0.f;
        }
        for (size_t i = gtid; i < (size_t)K2 * 32; i += gn) g_cat2[0][i] = 0.f;
        for (size_t i = gtid; i < BATCH * 1024; i += gn) { g_c1[i] = 0.f; g_c2[i] = 0.f; }
        for (size_t i = gtid; i < BATCH * TE; i += gn) g_awcum[i] = 0.f;
    }
    gridbar(target);

    // ---- main loop ----
    for (int t = 0; t < TD; t++) {
        int par = t & 1;
        float* c1p = g_cat1[par];
        float* c1q = g_cat1[par ^ 1];
        float* c2p = g_cat2[par];
        float* c2q = g_cat2[par ^ 1];

        gemm_cell(SMU, c1p, g_w1 + (size_t)blk * K1 * 16, K1 / 16, bl1, g_c1,
                  c1q + (size_t)768 * 32, c2p);
        gridbar(target);
        gemm_cell(SMU, c2p, g_w2 + (size_t)blk * K2 * 16, K2 / 16, bl2, g_c2,
                  c2q + (size_t)1024 * 32, (float*)0);
        gridbar(target);

        if (blk < BATCH) {
            float* sWloc = SMF;            // 4096
            float* sh2   = SMF + 4096;     // 1024 (contig with sctx)
            float* sctx  = SMF + 5120;     // 512
            float* sq    = SMF + 5632;     // 128
            float* sve   = SMF + 5760;     // 128
            float* scw   = SMF + 5888;     // 992
            float* scb   = SMF + 6880;     // 32
            float* sawc  = SMF + 6912;     // 256
            float* se    = SMF + 7168;     // 256
            float* saw   = SMF + 7424;     // 256
            float* sred  = SMF + 7680;     // 32
            float* spp   = SMF + 7712;     // 320
            float* su    = SMF + 8032;     // 512
            float* sqp   = SMF + 8544;     // 512

            for (int i = tid; i < 4096; i += NTHR) sWloc[i] = W_loc[i];
            for (int i = tid; i < 1024; i += NTHR)
                sh2[i] = c2q[(size_t)(1024 + i) * 32 + blk];
            for (int i = tid; i < 992; i += NTHR) scw[i] = conv_w[i];
            if (tid < 32) scb[tid] = conv_b[tid];
            if (tid < 128) sve[tid] = v_e[tid];
            if (tid < 256) sawc[tid] = g_awcum[blk * TE + tid];
            __syncthreads();

            // q = h2 @ W_q, 4-way k-split
            {
                int kq = tid >> 7, a = tid & 127;
                float acc = 0.f;
                const float* wq = W_q + (size_t)kq * 256 * 128 + a;
#pragma unroll 4
                for (int k = 0; k < 256; k++) acc += sh2[kq * 256 + k] * wq[k * 128];
                sqp[kq * 128 + a] = acc;
            }
            __syncthreads();
            if (tid < 128)
                sq[tid] = (sqp[tid] + sqp[128 + tid]) + (sqp[256 + tid] + sqp[384 + tid]);
            __syncthreads();

            // conv + energies: warp w16 handles slots w16*16..+15
            {
                int w16 = tid >> 5;
                for (int ti = 0; ti < 16; ti++) {
                    int tt = w16 * 16 + ti;
                    float u = scb[lane];
#pragma unroll
                    for (int j = 0; j < 31; j++) {
                        int idx = tt + j - 15;
                        float av = (idx >= 0 && idx < TE) ? sawc[idx] : 0.f;
                        u += av * scw[lane * 31 + j];
                    }
                    su[w16 * 32 + lane] = u;
                    __syncwarp();
                    float l0 = 0.f, l1 = 0.f, l2 = 0.f, l3 = 0.f;
#pragma unroll
                    for (int c = 0; c < 32; c++) {
                        float uc = su[w16 * 32 + c];
                        l0 += uc * sWloc[c * 128 + lane];
                        l1 += uc * sWloc[c * 128 + lane + 32];
                        l2 += uc * sWloc[c * 128 + lane + 64];
                        l3 += uc * sWloc[c * 128 + lane + 96];
                    }
                    const float* per = g_pe + ((size_t)(blk * TE + tt)) * 128;
                    float ep = tanhf(sq[lane] + l0 + per[lane]) * sve[lane]
                             + tanhf(sq[lane + 32] + l1 + per[lane + 32]) * sve[lane + 32]
                             + tanhf(sq[lane + 64] + l2 + per[lane + 64]) * sve[lane + 64]
                             + tanhf(sq[lane + 96] + l3 + per[lane + 96]) * sve[lane + 96];
#pragma unroll
                    for (int o = 16; o; o >>= 1)
                        ep += __shfl_xor_sync(0xffffffffu, ep, o);
                    if (lane == 0) se[tt] = ep;
                    __syncwarp();
                }
            }
            __syncthreads();

            // softmax over 256
            float e = 0.f, ex = 0.f;
            if (tid < 256) {
                e = se[tid];
                float m = e;
#pragma unroll
                for (int o = 16; o; o >>= 1)
                    m = fmaxf(m, __shfl_xor_sync(0xffffffffu, m, o));
                if (lane == 0) sred[tid >> 5] = m;
            }
            __syncthreads();
            if (tid < 256) {
                float mm = sred[0];
#pragma unroll
                for (int i = 1; i < 8; i++) mm = fmaxf(mm, sred[i]);
                ex = expf(e - mm);
            }
            __syncthreads();
            if (tid < 256) {
                float s = ex;
#pragma unroll
                for (int o = 16; o; o >>= 1)
                    s += __shfl_xor_sync(0xffffffffu, s, o);
                if (lane == 0) sred[tid >> 5] = s;
            }
            __syncthreads();
            if (tid < 256) {
                float ss = 0.f;
#pragma unroll
                for (int i = 0; i < 8; i++) ss += sred[i];
                float aw = ex / ss;
                saw[tid] = aw;
                g_awcum[blk * TE + tid] = sawc[tid] + aw;
            }
            __syncthreads();

            // context: one col per thread, write transposed into cat1-next
            {
                int c = tid;
                float acc = 0.f;
                const float* ib = inputs + (size_t)blk * TE * EDIM + c;
#pragma unroll 4
                for (int tt2 = 0; tt2 < 256; tt2++)
                    acc += saw[tt2] * ib[(size_t)tt2 * EDIM];
                sctx[c] = acc;
                c1q[(size_t)(256 + c) * 32 + blk] = acc;
            }
            if (t + 1 < TD && tid < 256)
                c1q[(size_t)tid * 32 + blk] = g_x[((size_t)(t + 1) * 32 + blk) * 256 + tid];
            __syncthreads();

            // out = concat(h2, ctx) @ Wp + bp  (4-way k-split)
            if (tid < 320) {
                int col = tid >> 2, qr = tid & 3, k0 = qr * 384;
                float acc = 0.f;
                const float* scat = sh2;
#pragma unroll 4
                for (int k = 0; k < 384; k++) acc += scat[k0 + k] * Wp[(k0 + k) * NM + col];
                spp[col * 4 + qr] = acc;
            }
            __syncthreads();
            if (tid < 80)
                out[(size_t)t * (BATCH * NM) + blk * NM + tid] =
                    ((spp[tid * 4] + spp[tid * 4 + 1]) +
                     (spp[tid * 4 + 2] + spp[tid * 4 + 3])) + bp[tid];
        }
        gridbar(target);
    }

    // ---- reset barrier state for deterministic replays ----
    __syncthreads();
    if (tid == 0) {
        __threadfence();
        atomicAdd(&g_done, 1u);
        if (blk == 0) {
            while (*((volatile unsigned*)&g_done) < NBLK) {}
            g_barcnt = 0;
            g_done = 0;
            __threadfence();
        }
    }
}

// ---------------- launch: ONE graph node ----------------
extern "C" void kernel_launch(void* const* d_in, const int* in_sizes, int n_in,
                              void* d_out, int out_size) {
    cudaFuncSetAttribute(decoder_kernel,
                         cudaFuncAttributeMaxDynamicSharedMemorySize, SMEM_BYTES);
    decoder_kernel<<<NBLK, NTHR, SMEM_BYTES>>>(
        (const float*)d_in[0],  (const float*)d_in[1],  (const float*)d_in[2],
        (const float*)d_in[3],  (const float*)d_in[4],  (const float*)d_in[5],
        (const float*)d_in[6],  (const float*)d_in[7],  (const float*)d_in[8],
        (const float*)d_in[9],  (const float*)d_in[10], (const float*)d_in[11],
        (const float*)d_in[12], (const float*)d_in[13], (const float*)d_in[14],
        (const float*)d_in[15], (const float*)d_in[16], (const float*)d_in[17],
        (const float*)d_in[18], (const float*)d_in[19], (float*)d_out);
}

// round 15
// speedup vs baseline: 2.3997x; 1.0943x over previous
#include <cuda_runtime.h>
#include <math.h>

typedef unsigned long long U64;

#define TD 200
#define BATCH 32
#define TE 256
#define EDIM 512
#define NM 80
#define K1 1792
#define K2 2048
#define NBLK 128
#define NTHR 512
#define SMEM_BYTES 65536

// ---------------- persistent device state ----------------
__device__ float g_x[TD * BATCH * 256];
__device__ float g_pe[BATCH * TE * 128];
__device__ U64 g_cat1[2][(size_t)K1 * 32];     // duplicated pairs (v,v), k-major [K][32]
__device__ U64 g_cat2[2][(size_t)K2 * 32];
__device__ float g_c1[BATCH * 1024];
__device__ float g_c2[BATCH * 1024];
__device__ float g_h2f[BATCH * 1024];          // float copy of h2 for ATT
__device__ float g_awcum[BATCH * TE];
__device__ float g_energ[BATCH * TE];
__device__ float g_wpt[NM * 1536];             // Wp transposed [col][k]
__device__ U64 g_w1[(size_t)NBLK * K1 * 16];
__device__ U64 g_w2[(size_t)NBLK * K2 * 16];
__device__ U64 g_barcnt;
__device__ unsigned g_done;

// ---------------- helpers ----------------
__device__ __forceinline__ U64 pk2(float x, float y) {
    U64 r; asm("mov.b64 %0, {%1, %2};" : "=l"(r) : "f"(x), "f"(y)); return r;
}
__device__ __forceinline__ void upk2(U64 v, float& lo, float& hi) {
    asm("mov.b64 {%0, %1}, %2;" : "=f"(lo), "=f"(hi) : "l"(v));
}
__device__ __forceinline__ void fma2(U64& d, U64 a, U64 b) {
    asm("fma.rn.f32x2 %0, %1, %2, %0;" : "+l"(d) : "l"(a), "l"(b));
}
__device__ __forceinline__ float sigm(float x) { return 1.f / (1.f + expf(-x)); }

__device__ __forceinline__ void gridbar(U64& target) {
    __threadfence();
    __syncthreads();
    if (threadIdx.x == 0) {
        target += NBLK;
        atomicAdd(&g_barcnt, 1ULL);
        while (*((volatile U64*)&g_barcnt) < target) {}
    }
    __syncthreads();
    __threadfence();
}

// ---------------- GEMM (M=32, 8 h-cols/block) + LSTM cell ----------------
__device__ void gemm_cell(U64* swr, const U64* __restrict__ A,
                          const U64* __restrict__ wp, int KS,
                          const float* __restrict__ bias,
                          float* __restrict__ cst,
                          U64* __restrict__ d1, U64* __restrict__ d2,
                          float* __restrict__ hf) {
    int tid = threadIdx.x, w = tid >> 5, lane = tid & 31;
    int rg = lane >> 3, hc = lane & 7;
    U64 c0 = 0, c1 = 0, c2 = 0, c3 = 0, c4 = 0, c5 = 0, c6 = 0, c7 = 0;
    U64 c8 = 0, c9 = 0, c10 = 0, c11 = 0, c12 = 0, c13 = 0, c14 = 0, c15 = 0;
    int kbeg = w * KS;
    const ulonglong2* ap = (const ulonglong2*)(A + (size_t)kbeg * 32) + rg * 4;
    const ulonglong2* wpp = (const ulonglong2*)(wp + (size_t)kbeg * 16) + hc;
#pragma unroll 4
    for (int k = 0; k < KS; k++) {
        ulonglong2 a0 = ap[0], a1 = ap[1], a2 = ap[2], a3 = ap[3];
        ulonglong2 wv = *wpp;
        ap += 16; wpp += 8;
        fma2(c0,  a0.x, wv.x); fma2(c1,  a0.x, wv.y);
        fma2(c2,  a0.y, wv.x); fma2(c3,  a0.y, wv.y);
        fma2(c4,  a1.x, wv.x); fma2(c5,  a1.x, wv.y);
        fma2(c6,  a1.y, wv.x); fma2(c7,  a1.y, wv.y);
        fma2(c8,  a2.x, wv.x); fma2(c9,  a2.x, wv.y);
        fma2(c10, a2.y, wv.x); fma2(c11, a2.y, wv.y);
        fma2(c12, a3.x, wv.x); fma2(c13, a3.x, wv.y);
        fma2(c14, a3.y, wv.x); fma2(c15, a3.y, wv.y);
    }
    U64* dst = swr + w * 512 + (rg * 8) * 16 + hc * 2;
    {
        ulonglong2 v;
        v.x = c0;  v.y = c1;  *(ulonglong2*)(dst + 0 * 16) = v;
        v.x = c2;  v.y = c3;  *(ulonglong2*)(dst + 1 * 16) = v;
        v.x = c4;  v.y = c5;  *(ulonglong2*)(dst + 2 * 16) = v;
        v.x = c6;  v.y = c7;  *(ulonglong2*)(dst + 3 * 16) = v;
        v.x = c8;  v.y = c9;  *(ulonglong2*)(dst + 4 * 16) = v;
        v.x = c10; v.y = c11; *(ulonglong2*)(dst + 5 * 16) = v;
        v.x = c12; v.y = c13; *(ulonglong2*)(dst + 6 * 16) = v;
        v.x = c14; v.y = c15; *(ulonglong2*)(dst + 7 * 16) = v;
    }
    __syncthreads();
    {
        float lo = 0.f, hi = 0.f;
#pragma unroll
        for (int ww = 0; ww < 16; ww++) {
            float l, h; upk2(swr[ww * 512 + tid], l, h);
            lo += l; hi += h;
        }
        __syncthreads();
        swr[tid] = pk2(lo, hi);
    }
    __syncthreads();
    if (tid < 256) {
        int row = tid >> 3, cc = tid & 7;
        int c = blockIdx.x * 8 + cc;
        float gi, gf, gg, go;
        upk2(swr[row * 16 + cc * 2], gi, gf);
        upk2(swr[row * 16 + cc * 2 + 1], gg, go);
        float ii = sigm(gi + bias[c]);
        float ff = sigm(gf + bias[1024 + c]);
        float gt = tanhf(gg + bias[2048 + c]);
        float oo = sigm(go + bias[3072 + c]);
        float cn = ff * cst[row * 1024 + c] + ii * gt;
        float hh = oo * tanhf(cn);
        cst[row * 1024 + c] = cn;
        U64 hd = pk2(hh, hh);
        d1[(size_t)c * 32 + row] = hd;
        if (d2) d2[(size_t)c * 32 + row] = hd;
        if (hf) hf[row * 1024 + c] = hh;
    }
    __syncthreads();
}

// ---------------- the whole decoder ----------------
__global__ void __launch_bounds__(NTHR, 1) decoder_kernel(
    const float* __restrict__ inputs, const float* __restrict__ pmels,
    const float* __restrict__ W_enc, const float* __restrict__ W_q,
    const float* __restrict__ conv_w, const float* __restrict__ conv_b,
    const float* __restrict__ W_loc, const float* __restrict__ v_e,
    const float* __restrict__ pw1, const float* __restrict__ pb1,
    const float* __restrict__ pw2, const float* __restrict__ pb2,
    const float* __restrict__ Wi1, const float* __restrict__ Wh1,
    const float* __restrict__ bl1, const float* __restrict__ Wi2,
    const float* __restrict__ Wh2, const float* __restrict__ bl2,
    const float* __restrict__ Wp, const float* __restrict__ bp,
    float* __restrict__ out) {
    extern __shared__ U64 SMU[];
    float* SMF = (float*)SMU;
    int tid = threadIdx.x, blk = blockIdx.x;
    int lane = tid & 31;
    size_t gtid = (size_t)blk * NTHR + tid;
    size_t gn = (size_t)NBLK * NTHR;
    U64 target = 0;

    // ---- P0: prenet ----
    {
        float* smel = SMF;
        float* sx1 = SMF + 256;
        int sub = tid >> 8, j = tid & 255;
        for (int tp = blk * 2; tp < TD * BATCH; tp += NBLK * 2) {
            int task = tp + sub;
            int t = task >> 5, b = task & 31;
            if (j < 80) smel[sub * 128 + j] =
                (t == 0) ? 0.f : pmels[(b * 80 + j) * TD + (t - 1)];
            __syncthreads();
            float a1 = pb1[j];
#pragma unroll 8
            for (int k = 0; k < 80; k++) a1 += smel[sub * 128 + k] * pw1[k * 256 + j];
            sx1[sub * 256 + j] = fmaxf(a1, 0.f);
            __syncthreads();
            float a2 = pb2[j];
#pragma unroll 8
            for (int k = 0; k < 256; k++) a2 += sx1[sub * 256 + k] * pw2[k * 256 + j];
            g_x[(size_t)task * 256 + j] = fmaxf(a2, 0.f);
            __syncthreads();
        }
    }
    gridbar(target);

    // ---- P1: proc_enc + weight repacks + state init ----
    {
        int sub = tid >> 7, a = tid & 127;
        for (int tp = blk * 4; tp < BATCH * TE; tp += NBLK * 4) {
            int task = tp + sub;
            const float* ip = inputs + (size_t)task * 512;
            float acc = 0.f;
#pragma unroll 8
            for (int k = 0; k < 512; k++) acc += ip[k] * W_enc[k * 128 + a];
            g_pe[(size_t)task * 128 + a] = acc;
        }
        size_t n1 = (size_t)NBLK * K1 * 16;
        for (size_t i = gtid; i < n1; i += gn) {
            int p = (int)(i & 1);
            int hc = (int)((i >> 1) & 7);
            size_t r = i >> 4;
            int k = (int)(r % K1);
            int b2 = (int)(r / K1);
            int c = b2 * 8 + hc;
            const float* Wr = (k < 768) ? (Wi1 + (size_t)k * 4096)
                                        : (Wh1 + (size_t)(k - 768) * 4096);
            g_w1[i] = pk2(Wr[(p * 2) * 1024 + c], Wr[(p * 2 + 1) * 1024 + c]);
        }
        size_t n2 = (size_t)NBLK * K2 * 16;
        for (size_t i = gtid; i < n2; i += gn) {
            int p = (int)(i & 1);
            int hc = (int)((i >> 1) & 7);
            size_t r = i >> 4;
            int k = (int)(r & (K2 - 1));
            int b2 = (int)(r >> 11);
            int c = b2 * 8 + hc;
            const float* Wr = (k < 1024) ? (Wi2 + (size_t)k * 4096)
                                         : (Wh2 + (size_t)(k - 1024) * 4096);
            g_w2[i] = pk2(Wr[(p * 2) * 1024 + c], Wr[(p * 2 + 1) * 1024 + c]);
        }
        for (size_t i = gtid; i < (size_t)NM * 1536; i += gn) {
            int col = (int)(i / 1536), k = (int)(i % 1536);
            g_wpt[i] = Wp[(size_t)k * NM + col];
        }
        for (size_t i = gtid; i < (size_t)K1 * 32; i += gn) {
            int k = (int)(i >> 5), b = (int)(i & 31);
            float v = (k < 256) ? g_x[(size_t)b * 256 + k] : 0.f;
            g_cat1[0][i] = pk2(v, v);
        }
        for (size_t i = gtid; i < (size_t)K2 * 32; i += gn) g_cat2[0][i] = 0;
        for (size_t i = gtid; i < BATCH * 1024; i += gn) { g_c1[i] = 0.f; g_c2[i] = 0.f; }
        for (size_t i = gtid; i < BATCH * TE; i += gn) g_awcum[i] = 0.f;
    }
    gridbar(target);

    // ---- main loop: 4 barriers/step ----
    for (int t = 0; t < TD; t++) {
        int par = t & 1;
        U64* c1p = g_cat1[par];
        U64* c1q = g_cat1[par ^ 1];
        U64* c2p = g_cat2[par];
        U64* c2q = g_cat2[par ^ 1];

        gemm_cell(SMU, c1p, g_w1 + (size_t)blk * K1 * 16, K1 / 16, bl1, g_c1,
                  c1q + (size_t)768 * 32, c2p, (float*)0);
        gridbar(target);
        gemm_cell(SMU, c2p, g_w2 + (size_t)blk * K2 * 16, K2 / 16, bl2, g_c2,
                  c2q + (size_t)1024 * 32, (U64*)0, g_h2f);
        gridbar(target);

        // ---- ATT-A: all 128 blocks; b = blk&31, chunk = blk>>5 ----
        {
            int b = blk & 31, chunk = blk >> 5;
            float* sWloc = SMF;            // 4096
            float* sh2   = SMF + 4096;     // 1024
            float* sq    = SMF + 5120;     // 128
            float* sve   = SMF + 5248;     // 128
            float* scw   = SMF + 5376;     // 992
            float* scb   = SMF + 6368;     // 32
            float* sawc  = SMF + 6400;     // 256
            float* su    = SMF + 6656;     // 512
            float* sqp   = SMF + 7168;     // 512

            for (int i = tid; i < 4096; i += NTHR) sWloc[i] = W_loc[i];
            for (int i = tid; i < 1024; i += NTHR) sh2[i] = g_h2f[b * 1024 + i];
            for (int i = tid; i < 992; i += NTHR) scw[i] = conv_w[i];
            if (tid < 32) scb[tid] = conv_b[tid];
            if (tid < 128) sve[tid] = v_e[tid];
            if (tid < 256) sawc[tid] = g_awcum[b * TE + tid];
            __syncthreads();

            // q = h2 @ W_q : 4-way k-split, deep ILP
            {
                int a = tid & 127, ks = tid >> 7;
                float q0 = 0.f, q1 = 0.f;
                const float* wq = W_q + (size_t)ks * 256 * 128 + a;
                const float* hh = sh2 + ks * 256;
#pragma unroll 16
                for (int k = 0; k < 256; k += 2) {
                    q0 += hh[k] * wq[(size_t)k * 128];
                    q1 += hh[k + 1] * wq[(size_t)(k + 1) * 128];
                }
                sqp[tid] = q0 + q1;
            }
            __syncthreads();
            if (tid < 128)
                sq[tid] = (sqp[tid] + sqp[128 + tid]) + (sqp[256 + tid] + sqp[384 + tid]);
            __syncthreads();

            // energies: warp handles 4 t-slots of this chunk
            {
                int w16 = tid >> 5;
                for (int ti = 0; ti < 4; ti++) {
                    int tt = chunk * 64 + w16 * 4 + ti;
                    float u = scb[lane];
#pragma unroll
                    for (int j = 0; j < 31; j++) {
                        int idx = tt + j - 15;
                        float av = (idx >= 0 && idx < TE) ? sawc[idx] : 0.f;
                        u += av * scw[lane * 31 + j];
                    }
                    su[w16 * 32 + lane] = u;
                    __syncwarp();
                    float l0 = 0.f, l1 = 0.f, l2 = 0.f, l3 = 0.f;
#pragma unroll
                    for (int c = 0; c < 32; c++) {
                        float uc = su[w16 * 32 + c];
                        l0 += uc * sWloc[c * 128 + lane];
                        l1 += uc * sWloc[c * 128 + lane + 32];
                        l2 += uc * sWloc[c * 128 + lane + 64];
                        l3 += uc * sWloc[c * 128 + lane + 96];
                    }
                    const float* per = g_pe + ((size_t)(b * TE + tt)) * 128;
                    float ep = tanhf(sq[lane] + l0 + per[lane]) * sve[lane]
                             + tanhf(sq[lane + 32] + l1 + per[lane + 32]) * sve[lane + 32]
                             + tanhf(sq[lane + 64] + l2 + per[lane + 64]) * sve[lane + 64]
                             + tanhf(sq[lane + 96] + l3 + per[lane + 96]) * sve[lane + 96];
#pragma unroll
                    for (int o = 16; o; o >>= 1)
                        ep += __shfl_xor_sync(0xffffffffu, ep, o);
                    if (lane == 0) g_energ[b * TE + tt] = ep;
                    __syncwarp();
                }
            }
        }
        gridbar(target);

        // ---- ATT-B: blocks 0..31 ----
        if (blk < BATCH) {
            float* scat = SMF;             // 1536: h2(1024) | ctx(512)
            float* saw  = SMF + 1536;      // 256
            float* sred = SMF + 1792;      // 8
            float* spp  = SMF + 1824;      // 320

            for (int i = tid; i < 1024; i += NTHR) scat[i] = g_h2f[blk * 1024 + i];
            __syncthreads();

            // softmax over 256 energies
            float e = 0.f, ex = 0.f;
            if (tid < 256) {
                e = g_energ[blk * TE + tid];
                float m = e;
#pragma unroll
                for (int o = 16; o; o >>= 1)
                    m = fmaxf(m, __shfl_xor_sync(0xffffffffu, m, o));
                if (lane == 0) sred[tid >> 5] = m;
            }
            __syncthreads();
            if (tid < 256) {
                float mm = sred[0];
#pragma unroll
                for (int i = 1; i < 8; i++) mm = fmaxf(mm, sred[i]);
                ex = expf(e - mm);
            }
            __syncthreads();
            if (tid < 256) {
                float s = ex;
#pragma unroll
                for (int o = 16; o; o >>= 1)
                    s += __shfl_xor_sync(0xffffffffu, s, o);
                if (lane == 0) sred[tid >> 5] = s;
            }
            __syncthreads();
            if (tid < 256) {
                float ss = 0.f;
#pragma unroll
                for (int i = 0; i < 8; i++) ss += sred[i];
                float aw = ex / ss;
                saw[tid] = aw;
                g_awcum[blk * TE + tid] += aw;
            }
            __syncthreads();

            // context: 1 col/thread, 2 accumulators, deep ILP
            {
                int c = tid;
                const float* ib = inputs + (size_t)blk * TE * EDIM + c;
                float a0 = 0.f, a1 = 0.f;
#pragma unroll 8
                for (int tt2 = 0; tt2 < 256; tt2 += 2) {
                    a0 += saw[tt2] * ib[(size_t)tt2 * EDIM];
                    a1 += saw[tt2 + 1] * ib[(size_t)(tt2 + 1) * EDIM];
                }
                float acc = a0 + a1;
                scat[1024 + c] = acc;
                U64* c1q2 = g_cat1[(t & 1) ^ 1];
                c1q2[(size_t)(256 + c) * 32 + blk] = pk2(acc, acc);
            }
            if (t + 1 < TD && tid < 256) {
                float xv = g_x[((size_t)(t + 1) * 32 + blk) * 256 + tid];
                U64* c1q2 = g_cat1[(t & 1) ^ 1];
                c1q2[(size_t)tid * 32 + blk] = pk2(xv, xv);
            }
            __syncthreads();

            // out = concat(h2, ctx) @ Wp + bp  (transposed Wp, float4)
            if (tid < 320) {
                int col = tid >> 2, qr = tid & 3, k0 = qr * 384;
                const float4* wp4 = (const float4*)(g_wpt + (size_t)col * 1536 + k0);
                const float4* sc4 = (const float4*)(scat + k0);
                float acc = 0.f;
#pragma unroll 8
                for (int j = 0; j < 96; j++) {
                    float4 wv = wp4[j];
                    float4 sv = sc4[j];
                    acc += wv.x * sv.x + wv.y * sv.y + wv.z * sv.z + wv.w * sv.w;
                }
                spp[col * 4 + qr] = acc;
            }
            __syncthreads();
            if (tid < 80)
                out[(size_t)t * (BATCH * NM) + blk * NM + tid] =
                    ((spp[tid * 4] + spp[tid * 4 + 1]) +
                     (spp[tid * 4 + 2] + spp[tid * 4 + 3])) + bp[tid];
        }
        gridbar(target);
    }

    // ---- reset barrier state ----
    __syncthreads();
    if (tid == 0) {
        __threadfence();
        atomicAdd(&g_done, 1u);
        if (blk == 0) {
            while (*((volatile unsigned*)&g_done) < NBLK) {}
            g_barcnt = 0;
            g_done = 0;
            __threadfence();
        }
    }
}

// ---------------- launch ----------------
extern "C" void kernel_launch(void* const* d_in, const int* in_sizes, int n_in,
                              void* d_out, int out_size) {
    cudaFuncSetAttribute(decoder_kernel,
                         cudaFuncAttributeMaxDynamicSharedMemorySize, SMEM_BYTES);
    decoder_kernel<<<NBLK, NTHR, SMEM_BYTES>>>(
        (const float*)d_in[0],  (const float*)d_in[1],  (const float*)d_in[2],
        (const float*)d_in[3],  (const float*)d_in[4],  (const float*)d_in[5],
        (const float*)d_in[6],  (const float*)d_in[7],  (const float*)d_in[8],
        (const float*)d_in[9],  (const float*)d_in[10], (const float*)d_in[11],
        (const float*)d_in[12], (const float*)d_in[13], (const float*)d_in[14],
        (const float*)d_in[15], (const float*)d_in[16], (const float*)d_in[17],
        (const float*)d_in[18], (const float*)d_in[19], (float*)d_out);
}

// round 17
// speedup vs baseline: 3.0906x; 1.2879x over previous
#include <cuda_runtime.h>
#include <math.h>

typedef unsigned long long U64;

#define TD 200
#define BATCH 32
#define TE 256
#define EDIM 512
#define NM 80
#define K1 1792
#define K2 2048
#define NBLK 128
#define NTHR 512
#define SMEM_BYTES 65536

// ---------------- persistent device state ----------------
__device__ float g_x[TD * BATCH * 256];
__device__ float g_pe[BATCH * TE * 128];
__device__ float g_cat1[2][(size_t)K1 * 32];   // fp32, k-major [K][32]
__device__ float g_cat2[2][(size_t)K2 * 32];
__device__ float g_c1[BATCH * 1024];
__device__ float g_c2[BATCH * 1024];
__device__ float g_h2f[BATCH * 1024];
__device__ float g_awcum[BATCH * TE];
__device__ float g_energ[BATCH * TE];
__device__ float g_wpt[NM * 1536];             // Wp transposed [col][k]
__device__ U64 g_w1[(size_t)NBLK * K1 * 16];   // [blk][k][hc(8)][pair(2)]
__device__ U64 g_w2[(size_t)NBLK * K2 * 16];
__device__ U64 g_barcnt;
__device__ unsigned g_done;

// ---------------- helpers ----------------
__device__ __forceinline__ U64 pk2(float x, float y) {
    U64 r; asm("mov.b64 %0, {%1, %2};" : "=l"(r) : "f"(x), "f"(y)); return r;
}
__device__ __forceinline__ void upk2(U64 v, float& lo, float& hi) {
    asm("mov.b64 {%0, %1}, %2;" : "=f"(lo), "=f"(hi) : "l"(v));
}
__device__ __forceinline__ void fma2(U64& d, U64 a, U64 b) {
    asm("fma.rn.f32x2 %0, %1, %2, %0;" : "+l"(d) : "l"(a), "l"(b));
}
__device__ __forceinline__ float sigm(float x) { return 1.f / (1.f + expf(-x)); }

__device__ __forceinline__ void gridbar(U64& target) {
    __threadfence();
    __syncthreads();
    if (threadIdx.x == 0) {
        target += NBLK;
        atomicAdd(&g_barcnt, 1ULL);
        while (*((volatile U64*)&g_barcnt) < target) {}
    }
    __syncthreads();
    __threadfence();
}

// ---------------- GEMM (M=32, 8 h-cols/block) + LSTM cell ----------------
// Warp w covers k = w (mod 16). A staged per 64-k tile into smem as
// duplicated (v,v) U64 pairs, double-buffered. Per k: 4 LDS.128 + 1 LDG.128
// (weights) + 16 FFMA2. Cross-warp reduction via 64KB smem (union with tiles).
__device__ void gemm_cell(U64* SMU, const float* __restrict__ A,
                          const U64* __restrict__ wp, int NT,
                          const float* __restrict__ bias,
                          float* __restrict__ cst,
                          float* __restrict__ d1, float* __restrict__ d2,
                          float* __restrict__ hf) {
    int tid = threadIdx.x, w = tid >> 5, lane = tid & 31;
    int rg = lane >> 3, hc = lane & 7;
    int ckk = tid >> 3, cr4 = (tid & 7) * 4;          // copy mapping
    U64 c0 = 0, c1 = 0, c2 = 0, c3 = 0, c4 = 0, c5 = 0, c6 = 0, c7 = 0;
    U64 c8 = 0, c9 = 0, c10 = 0, c11 = 0, c12 = 0, c13 = 0, c14 = 0, c15 = 0;

    // prologue: stage tile 0
    {
        float4 v = ((const float4*)A)[tid];
        U64* d = SMU + ckk * 32 + cr4;
        d[0] = pk2(v.x, v.x); d[1] = pk2(v.y, v.y);
        d[2] = pk2(v.z, v.z); d[3] = pk2(v.w, v.w);
    }
    __syncthreads();

    for (int t = 0; t < NT; t++) {
        if (t + 1 < NT) {
            float4 v = ((const float4*)(A + (size_t)(t + 1) * 2048))[tid];
            U64* d = SMU + (((t + 1) & 1) * 2048) + ckk * 32 + cr4;
            d[0] = pk2(v.x, v.x); d[1] = pk2(v.y, v.y);
            d[2] = pk2(v.z, v.z); d[3] = pk2(v.w, v.w);
        }
        const U64* ab = SMU + (t & 1) * 2048;
        const U64* wb = wp + (size_t)t * 64 * 16;
#pragma unroll
        for (int j = 0; j < 4; j++) {
            int kk = w + 16 * j;
            const ulonglong2* ar = (const ulonglong2*)(ab + kk * 32 + rg * 8);
            ulonglong2 a0 = ar[0], a1 = ar[1], a2 = ar[2], a3 = ar[3];
            ulonglong2 wv = *(const ulonglong2*)(wb + (size_t)kk * 16 + hc * 2);
            fma2(c0,  a0.x, wv.x); fma2(c1,  a0.x, wv.y);
            fma2(c2,  a0.y, wv.x); fma2(c3,  a0.y, wv.y);
            fma2(c4,  a1.x, wv.x); fma2(c5,  a1.x, wv.y);
            fma2(c6,  a1.y, wv.x); fma2(c7,  a1.y, wv.y);
            fma2(c8,  a2.x, wv.x); fma2(c9,  a2.x, wv.y);
            fma2(c10, a2.y, wv.x); fma2(c11, a2.y, wv.y);
            fma2(c12, a3.x, wv.x); fma2(c13, a3.x, wv.y);
            fma2(c14, a3.y, wv.x); fma2(c15, a3.y, wv.y);
        }
        __syncthreads();
    }

    // per-warp partials into smem (region overlaps tiles; all reads done)
    U64* dst = SMU + w * 512 + (rg * 8) * 16 + hc * 2;
    {
        ulonglong2 v;
        v.x = c0;  v.y = c1;  *(ulonglong2*)(dst + 0 * 16) = v;
        v.x = c2;  v.y = c3;  *(ulonglong2*)(dst + 1 * 16) = v;
        v.x = c4;  v.y = c5;  *(ulonglong2*)(dst + 2 * 16) = v;
        v.x = c6;  v.y = c7;  *(ulonglong2*)(dst + 3 * 16) = v;
        v.x = c8;  v.y = c9;  *(ulonglong2*)(dst + 4 * 16) = v;
        v.x = c10; v.y = c11; *(ulonglong2*)(dst + 5 * 16) = v;
        v.x = c12; v.y = c13; *(ulonglong2*)(dst + 6 * 16) = v;
        v.x = c14; v.y = c15; *(ulonglong2*)(dst + 7 * 16) = v;
    }
    __syncthreads();
    {
        float lo = 0.f, hi = 0.f;
#pragma unroll
        for (int ww = 0; ww < 16; ww++) {
            float l, h; upk2(SMU[ww * 512 + tid], l, h);
            lo += l; hi += h;
        }
        __syncthreads();
        SMU[tid] = pk2(lo, hi);
    }
    __syncthreads();
    if (tid < 256) {
        int row = tid >> 3, cc = tid & 7;
        int c = blockIdx.x * 8 + cc;
        float gi, gf, gg, go;
        upk2(SMU[row * 16 + cc * 2], gi, gf);
        upk2(SMU[row * 16 + cc * 2 + 1], gg, go);
        float ii = sigm(gi + bias[c]);
        float ff = sigm(gf + bias[1024 + c]);
        float gt = tanhf(gg + bias[2048 + c]);
        float oo = sigm(go + bias[3072 + c]);
        float cn = ff * cst[row * 1024 + c] + ii * gt;
        float hh = oo * tanhf(cn);
        cst[row * 1024 + c] = cn;
        d1[(size_t)c * 32 + row] = hh;
        if (d2) d2[(size_t)c * 32 + row] = hh;
        if (hf) hf[row * 1024 + c] = hh;
    }
    __syncthreads();
}

// ---------------- the whole decoder ----------------
__global__ void __launch_bounds__(NTHR, 1) decoder_kernel(
    const float* __restrict__ inputs, const float* __restrict__ pmels,
    const float* __restrict__ W_enc, const float* __restrict__ W_q,
    const float* __restrict__ conv_w, const float* __restrict__ conv_b,
    const float* __restrict__ W_loc, const float* __restrict__ v_e,
    const float* __restrict__ pw1, const float* __restrict__ pb1,
    const float* __restrict__ pw2, const float* __restrict__ pb2,
    const float* __restrict__ Wi1, const float* __restrict__ Wh1,
    const float* __restrict__ bl1, const float* __restrict__ Wi2,
    const float* __restrict__ Wh2, const float* __restrict__ bl2,
    const float* __restrict__ Wp, const float* __restrict__ bp,
    float* __restrict__ out) {
    extern __shared__ U64 SMU[];
    float* SMF = (float*)SMU;
    int tid = threadIdx.x, blk = blockIdx.x;
    int lane = tid & 31;
    size_t gtid = (size_t)blk * NTHR + tid;
    size_t gn = (size_t)NBLK * NTHR;
    U64 target = 0;

    // ---- P0: prenet ----
    {
        float* smel = SMF;
        float* sx1 = SMF + 256;
        int sub = tid >> 8, j = tid & 255;
        for (int tp = blk * 2; tp < TD * BATCH; tp += NBLK * 2) {
            int task = tp + sub;
            int t = task >> 5, b = task & 31;
            if (j < 80) smel[sub * 128 + j] =
                (t == 0) ? 0.f : pmels[(b * 80 + j) * TD + (t - 1)];
            __syncthreads();
            float a1 = pb1[j];
#pragma unroll 8
            for (int k = 0; k < 80; k++) a1 += smel[sub * 128 + k] * pw1[k * 256 + j];
            sx1[sub * 256 + j] = fmaxf(a1, 0.f);
            __syncthreads();
            float a2 = pb2[j];
#pragma unroll 8
            for (int k = 0; k < 256; k++) a2 += sx1[sub * 256 + k] * pw2[k * 256 + j];
            g_x[(size_t)task * 256 + j] = fmaxf(a2, 0.f);
            __syncthreads();
        }
    }
    gridbar(target);

    // ---- P1: proc_enc + weight repacks + state init ----
    {
        int sub = tid >> 7, a = tid & 127;
        for (int tp = blk * 4; tp < BATCH * TE; tp += NBLK * 4) {
            int task = tp + sub;
            const float* ip = inputs + (size_t)task * 512;
            float acc = 0.f;
#pragma unroll 8
            for (int k = 0; k < 512; k++) acc += ip[k] * W_enc[k * 128 + a];
            g_pe[(size_t)task * 128 + a] = acc;
        }
        size_t n1 = (size_t)NBLK * K1 * 16;
        for (size_t i = gtid; i < n1; i += gn) {
            int p = (int)(i & 1);
            int hc = (int)((i >> 1) & 7);
            size_t r = i >> 4;
            int k = (int)(r % K1);
            int b2 = (int)(r / K1);
            int c = b2 * 8 + hc;
            const float* Wr = (k < 768) ? (Wi1 + (size_t)k * 4096)
                                        : (Wh1 + (size_t)(k - 768) * 4096);
            g_w1[i] = pk2(Wr[(p * 2) * 1024 + c], Wr[(p * 2 + 1) * 1024 + c]);
        }
        size_t n2 = (size_t)NBLK * K2 * 16;
        for (size_t i = gtid; i < n2; i += gn) {
            int p = (int)(i & 1);
            int hc = (int)((i >> 1) & 7);
            size_t r = i >> 4;
            int k = (int)(r & (K2 - 1));
            int b2 = (int)(r >> 11);
            int c = b2 * 8 + hc;
            const float* Wr = (k < 1024) ? (Wi2 + (size_t)k * 4096)
                                         : (Wh2 + (size_t)(k - 1024) * 4096);
            g_w2[i] = pk2(Wr[(p * 2) * 1024 + c], Wr[(p * 2 + 1) * 1024 + c]);
        }
        for (size_t i = gtid; i < (size_t)NM * 1536; i += gn) {
            int col = (int)(i / 1536), k = (int)(i % 1536);
            g_wpt[i] = Wp[(size_t)k * NM + col];
        }
        for (size_t i = gtid; i < (size_t)K1 * 32; i += gn) {
            int k = (int)(i >> 5), b = (int)(i & 31);
            g_cat1[0][i] = (k < 256) ? g_x[(size_t)b * 256 + k] : 0.f;
        }
        for (size_t i = gtid; i < (size_t)K2 * 32; i += gn) g_cat2[0][i] = 0.f;
        for (size_t i = gtid; i < BATCH * 1024; i += gn) { g_c1[i] = 0.f; g_c2[i] = 0.f; }
        for (size_t i = gtid; i < BATCH * TE; i += gn) g_awcum[i] = 0.f;
    }
    gridbar(target);

    // ---- main loop: 4 barriers/step ----
    for (int t = 0; t < TD; t++) {
        int par = t & 1;
        float* c1p = g_cat1[par];
        float* c1q = g_cat1[par ^ 1];
        float* c2p = g_cat2[par];
        float* c2q = g_cat2[par ^ 1];

        gemm_cell(SMU, c1p, g_w1 + (size_t)blk * K1 * 16, K1 / 64, bl1, g_c1,
                  c1q + (size_t)768 * 32, c2p, (float*)0);
        gridbar(target);
        gemm_cell(SMU, c2p, g_w2 + (size_t)blk * K2 * 16, K2 / 64, bl2, g_c2,
                  c2q + (size_t)1024 * 32, (float*)0, g_h2f);
        gridbar(target);

        // ---- ATT-A: all 128 blocks; b = blk&31, chunk = blk>>5 ----
        {
            int b = blk & 31, chunk = blk >> 5;
            float* sWloc = SMF;            // 4096
            float* sh2   = SMF + 4096;     // 1024
            float* sq    = SMF + 5120;     // 128
            float* sve   = SMF + 5248;     // 128
            float* scw   = SMF + 5376;     // 992
            float* scb   = SMF + 6368;     // 32
            float* sawc  = SMF + 6400;     // 256
            float* su    = SMF + 6656;     // 512
            float* sqp   = SMF + 7168;     // 512

            for (int i = tid; i < 4096; i += NTHR) sWloc[i] = W_loc[i];
            for (int i = tid; i < 1024; i += NTHR) sh2[i] = g_h2f[b * 1024 + i];
            for (int i = tid; i < 992; i += NTHR) scw[i] = conv_w[i];
            if (tid < 32) scb[tid] = conv_b[tid];
            if (tid < 128) sve[tid] = v_e[tid];
            if (tid < 256) sawc[tid] = g_awcum[b * TE + tid];
            __syncthreads();

            // q = h2 @ W_q : 4-way k-split
            {
                int a = tid & 127, ks = tid >> 7;
                float q0 = 0.f, q1 = 0.f;
                const float* wq = W_q + (size_t)ks * 256 * 128 + a;
                const float* hh = sh2 + ks * 256;
#pragma unroll 16
                for (int k = 0; k < 256; k += 2) {
                    q0 += hh[k] * wq[(size_t)k * 128];
                    q1 += hh[k + 1] * wq[(size_t)(k + 1) * 128];
                }
                sqp[tid] = q0 + q1;
            }
            __syncthreads();
            if (tid < 128)
                sq[tid] = (sqp[tid] + sqp[128 + tid]) + (sqp[256 + tid] + sqp[384 + tid]);
            __syncthreads();

            // energies: warp handles 4 t-slots of this 64-slot chunk
            {
                int w16 = tid >> 5;
                for (int ti = 0; ti < 4; ti++) {
                    int tt = chunk * 64 + w16 * 4 + ti;
                    float u = scb[lane];
#pragma unroll
                    for (int j = 0; j < 31; j++) {
                        int idx = tt + j - 15;
                        float av = (idx >= 0 && idx < TE) ? sawc[idx] : 0.f;
                        u += av * scw[lane * 31 + j];
                    }
                    su[w16 * 32 + lane] = u;
                    __syncwarp();
                    float l0 = 0.f, l1 = 0.f, l2 = 0.f, l3 = 0.f;
#pragma unroll
                    for (int c = 0; c < 32; c++) {
                        float uc = su[w16 * 32 + c];
                        l0 += uc * sWloc[c * 128 + lane];
                        l1 += uc * sWloc[c * 128 + lane + 32];
                        l2 += uc * sWloc[c * 128 + lane + 64];
                        l3 += uc * sWloc[c * 128 + lane + 96];
                    }
                    const float* per = g_pe + ((size_t)(b * TE + tt)) * 128;
                    float ep = tanhf(sq[lane] + l0 + per[lane]) * sve[lane]
                             + tanhf(sq[lane + 32] + l1 + per[lane + 32]) * sve[lane + 32]
                             + tanhf(sq[lane + 64] + l2 + per[lane + 64]) * sve[lane + 64]
                             + tanhf(sq[lane + 96] + l3 + per[lane + 96]) * sve[lane + 96];
#pragma unroll
                    for (int o = 16; o; o >>= 1)
                        ep += __shfl_xor_sync(0xffffffffu, ep, o);
                    if (lane == 0) g_energ[b * TE + tt] = ep;
                    __syncwarp();
                }
            }
        }
        gridbar(target);

        // ---- ATT-B: blocks 0..31 ----
        if (blk < BATCH) {
            float* scat = SMF;             // 1536: h2(1024) | ctx(512)
            float* saw  = SMF + 1536;      // 256
            float* sred = SMF + 1792;      // 8
            float* spp  = SMF + 1824;      // 320

            for (int i = tid; i < 1024; i += NTHR) scat[i] = g_h2f[blk * 1024 + i];
            __syncthreads();

            float e = 0.f, ex = 0.f;
            if (tid < 256) {
                e = g_energ[blk * TE + tid];
                float m = e;
#pragma unroll
                for (int o = 16; o; o >>= 1)
                    m = fmaxf(m, __shfl_xor_sync(0xffffffffu, m, o));
                if (lane == 0) sred[tid >> 5] = m;
            }
            __syncthreads();
            if (tid < 256) {
                float mm = sred[0];
#pragma unroll
                for (int i = 1; i < 8; i++) mm = fmaxf(mm, sred[i]);
                ex = expf(e - mm);
            }
            __syncthreads();
            if (tid < 256) {
                float s = ex;
#pragma unroll
                for (int o = 16; o; o >>= 1)
                    s += __shfl_xor_sync(0xffffffffu, s, o);
                if (lane == 0) sred[tid >> 5] = s;
            }
            __syncthreads();
            if (tid < 256) {
                float ss = 0.f;
#pragma unroll
                for (int i = 0; i < 8; i++) ss += sred[i];
                float aw = ex / ss;
                saw[tid] = aw;
                g_awcum[blk * TE + tid] += aw;
            }
            __syncthreads();

            // context: 1 col/thread
            {
                int c = tid;
                const float* ib = inputs + (size_t)blk * TE * EDIM + c;
                float a0 = 0.f, a1 = 0.f;
#pragma unroll 8
                for (int tt2 = 0; tt2 < 256; tt2 += 2) {
                    a0 += saw[tt2] * ib[(size_t)tt2 * EDIM];
                    a1 += saw[tt2 + 1] * ib[(size_t)(tt2 + 1) * EDIM];
                }
                float acc = a0 + a1;
                scat[1024 + c] = acc;
                float* c1q2 = g_cat1[(t & 1) ^ 1];
                c1q2[(size_t)(256 + c) * 32 + blk] = acc;
            }
            if (t + 1 < TD && tid < 256) {
                float* c1q2 = g_cat1[(t & 1) ^ 1];
                c1q2[(size_t)tid * 32 + blk] = g_x[((size_t)(t + 1) * 32 + blk) * 256 + tid];
            }
            __syncthreads();

            // out = concat(h2, ctx) @ Wp + bp  (transposed Wp, float4)
            if (tid < 320) {
                int col = tid >> 2, qr = tid & 3, k0 = qr * 384;
                const float4* wp4 = (const float4*)(g_wpt + (size_t)col * 1536 + k0);
                const float4* sc4 = (const float4*)(scat + k0);
                float acc = 0.f;
#pragma unroll 8
                for (int j = 0; j < 96; j++) {
                    float4 wv = wp4[j];
                    float4 sv = sc4[j];
                    acc += wv.x * sv.x + wv.y * sv.y + wv.z * sv.z + wv.w * sv.w;
                }
                spp[col * 4 + qr] = acc;
            }
            __syncthreads();
            if (tid < 80)
                out[(size_t)t * (BATCH * NM) + blk * NM + tid] =
                    ((spp[tid * 4] + spp[tid * 4 + 1]) +
                     (spp[tid * 4 + 2] + spp[tid * 4 + 3])) + bp[tid];
        }
        gridbar(target);
    }

    // ---- reset barrier state ----
    __syncthreads();
    if (tid == 0) {
        __threadfence();
        atomicAdd(&g_done, 1u);
        if (blk == 0) {
            while (*((volatile unsigned*)&g_done) < NBLK) {}
            g_barcnt = 0;
            g_done = 0;
            __threadfence();
        }
    }
}

// ---------------- launch ----------------
extern "C" void kernel_launch(void* const* d_in, const int* in_sizes, int n_in,
                              void* d_out, int out_size) {
    cudaFuncSetAttribute(decoder_kernel,
                         cudaFuncAttributeMaxDynamicSharedMemorySize, SMEM_BYTES);
    decoder_kernel<<<NBLK, NTHR, SMEM_BYTES>>>(
        (const float*)d_in[0],  (const float*)d_in[1],  (const float*)d_in[2],
        (const float*)d_in[3],  (const float*)d_in[4],  (const float*)d_in[5],
        (const float*)d_in[6],  (const float*)d_in[7],  (const float*)d_in[8],
        (const float*)d_in[9],  (const float*)d_in[10], (const float*)d_in[11],
        (const float*)d_in[12], (const float*)d_in[13], (const float*)d_in[14],
        (const float*)d_in[15], (const float*)d_in[16], (const float*)d_in[17],
        (const float*)d_in[18], (const float*)d_in[19], (float*)d_out);
}